// round 15
// baseline (speedup 1.0000x reference)
#include <cuda_runtime.h>
#include <cuda_fp16.h>
#include <cstdint>
#include <math.h>

#define B_TOT 512
#define SEQ   392
#define CH    128
#define NHEAD 4
#define HD    32
#define NWIN  128
#define MROWS 200704               // B_TOT*SEQ
#define NN    (SEQ*SEQ)            // 153664
#define QKV_SCALE 0.17677669529663687f
#define LOG2E 1.4426950408889634f
#define QS_LOG2E (QKV_SCALE*LOG2E)

#define NT16  25                   // 24 full 16-col tiles + tail (8 cols)
#define KSS   40                   // K smem stride (halves)
#define KS_ROWS 400
#define VTS   408                  // V^T smem stride (halves)
#define GSTR  136                  // gemm smem stride (halves)
#define GSMEM_QKV ((64 + 2*128) * GSTR * 2)   // X + double-buffered W = 87040 B
#define GSMEM_PRJ ((64 + 128) * GSTR * 2)     // 52224 B

// -------- scratch (device globals: no allocations allowed) --------
__device__ __half g_qkvwh[384*CH];
__device__ __half g_projwh[CH*CH];
__device__ __half g_q[(size_t)B_TOT*NHEAD*SEQ*HD];
__device__ __half g_k[(size_t)B_TOT*NHEAD*SEQ*HD];
__device__ __half g_v[(size_t)B_TOT*NHEAD*SEQ*HD];
__device__ __half g_ao[(size_t)MROWS*CH];
__device__ __half g_bias[(size_t)NHEAD*NN + 64];  // fp16, pre-scaled by log2e
__device__ int    g_mflag[NWIN];

// ============================================================
__device__ __forceinline__ uint32_t pack_h2(float lo, float hi) {
    uint32_t r;
    asm("cvt.rn.f16x2.f32 %0, %1, %2;" : "=r"(r) : "f"(hi), "f"(lo));
    return r;
}
__device__ __forceinline__ float ex2f(float x) {
    float y;
    asm("ex2.approx.f32 %0, %1;" : "=f"(y) : "f"(x));
    return y;
}
__device__ __forceinline__ uint32_t smem_u32(const void* p) {
    uint32_t a;
    asm("{ .reg .u64 t; cvta.to.shared.u64 t, %1; cvt.u32.u64 %0, t; }" : "=r"(a) : "l"(p));
    return a;
}
__device__ __forceinline__ void mma_f16(float& d0, float& d1, float& d2, float& d3,
                                        uint32_t a0, uint32_t a1, uint32_t a2, uint32_t a3,
                                        uint32_t b0, uint32_t b1) {
    asm volatile("mma.sync.aligned.m16n8k16.row.col.f32.f16.f16.f32 "
                 "{%0,%1,%2,%3}, {%4,%5,%6,%7}, {%8,%9}, {%0,%1,%2,%3};"
                 : "+f"(d0), "+f"(d1), "+f"(d2), "+f"(d3)
                 : "r"(a0), "r"(a1), "r"(a2), "r"(a3), "r"(b0), "r"(b1));
}
__device__ __forceinline__ void ldsm_x4(uint32_t& r0, uint32_t& r1, uint32_t& r2, uint32_t& r3,
                                        uint32_t addr) {
    asm volatile("ldmatrix.sync.aligned.m8n8.x4.shared.b16 {%0,%1,%2,%3}, [%4];"
                 : "=r"(r0), "=r"(r1), "=r"(r2), "=r"(r3) : "r"(addr));
}
#define CP_ASYNC16(sa, gp) \
    asm volatile("cp.async.ca.shared.global [%0], [%1], 16;" :: "r"(sa), "l"(gp) : "memory")
#define CP_COMMIT() asm volatile("cp.async.commit_group;" ::: "memory")
#define CP_WAIT0()  asm volatile("cp.async.wait_group 0;" ::: "memory")

// ============================================================
// Prep kernels
// ============================================================
__global__ void convert_w_kernel(const float* __restrict__ qkv_w,
                                 const float* __restrict__ proj_w) {
    if (blockIdx.x == 0 && threadIdx.x < NWIN) g_mflag[threadIdx.x] = 0;
    int t = blockIdx.x * 256 + threadIdx.x;   // 8 elems/thread
    const int QN = 384 * CH / 8;              // 6144
    const float* src; __half* dst; int i;
    if (t < QN) { src = qkv_w; dst = g_qkvwh; i = t; }
    else { src = proj_w; dst = g_projwh; i = t - QN; if (i >= CH * CH / 8) return; }
    float4 a = *(const float4*)(src + i * 8);
    float4 b = *(const float4*)(src + i * 8 + 4);
    uint4 o;
    o.x = pack_h2(a.x, a.y); o.y = pack_h2(a.z, a.w);
    o.z = pack_h2(b.x, b.y); o.w = pack_h2(b.z, b.w);
    *(uint4*)(dst + i * 8) = o;
}
__global__ void bias_gather_kernel(const float* __restrict__ table,
                                   const int* __restrict__ ridx) {
    int t = blockIdx.x * 256 + threadIdx.x;
    if (t >= NN) return;
    int r = ridx[t];
    float4 tv = *(const float4*)(table + (size_t)r * 4);
    g_bias[0 * (size_t)NN + t] = __float2half(tv.x * LOG2E);
    g_bias[1 * (size_t)NN + t] = __float2half(tv.y * LOG2E);
    g_bias[2 * (size_t)NN + t] = __float2half(tv.z * LOG2E);
    g_bias[3 * (size_t)NN + t] = __float2half(tv.w * LOG2E);
}
// grid (NWIN, 32): NN = 32 * 4802 exactly
__global__ void maskflag_kernel(const float* __restrict__ mask) {
    int w = blockIdx.x;
    int slice = blockIdx.y;
    const int SL = NN / 32;                   // 4802
    const float* mp = mask + (size_t)w * NN + (size_t)slice * SL;
    int any = 0;
    for (int i = threadIdx.x; i < SL; i += 256)
        any |= (mp[i] != 0.0f);
    any = __syncthreads_or(any);
    if (threadIdx.x == 0 && any) atomicOr(&g_mflag[w], 1);
}

// ============================================================
// Fused qkv GEMM: fp32 x read once (convert while staging);
// 3 qkv column-tiles looped in-kernel with cp.async
// double-buffered W staging (latency hidden under compute).
// ============================================================
__global__ void __launch_bounds__(256) gemm_qkv(const float* __restrict__ x) {
    extern __shared__ __half gsm[];
    __half* Xs = gsm;                         // [64][GSTR]
    __half* Wb[2] = { gsm + 64 * GSTR, gsm + (64 + 128) * GSTR };

    int m0 = blockIdx.x * 64;
    int tid = threadIdx.x, lane = tid & 31, warp = tid >> 5;
    int wm = warp >> 1, wn = warp & 1;
    int grp = lane >> 2, q4 = lane & 3;

    // per-thread W staging coords (8 x 16B per buffer fill)
    int wrow = tid >> 4, wcol = tid & 15;     // rows wrow..wrow+112 step 16? no:
    // s = tid + it*256 -> row = s>>4 (0..127), c = s&15

    // ---- issue cp.async for W tile 0 ----
#pragma unroll
    for (int it = 0; it < 8; it++) {
        int s = tid + it * 256;
        int row = s >> 4, c = s & 15;
        CP_ASYNC16(smem_u32(Wb[0] + row * GSTR + c * 8),
                   g_qkvwh + (size_t)row * CH + c * 8);
    }
    CP_COMMIT();

    // ---- stage X (fp32 -> fp16) meanwhile ----
#pragma unroll
    for (int s = tid; s < 2048; s += 256) {
        int row = s >> 5, c = s & 31;
        float4 xv = *(const float4*)(x + (size_t)(m0 + row) * CH + c * 4);
        uint2 p;
        p.x = pack_h2(xv.x, xv.y);
        p.y = pack_h2(xv.z, xv.w);
        *(uint2*)(Xs + row * GSTR + c * 4) = p;
    }
    CP_WAIT0();
    __syncthreads();

    int tg = lane >> 3, tr = lane & 7;
    uint32_t xbse = smem_u32(Xs + (wm * 16 + ((tg & 1) ? 8 : 0) + tr) * GSTR + ((tg & 2) ? 8 : 0));

    int r0 = m0 + wm * 16 + grp;
    int r1 = r0 + 8;
    int b0i = r0 / SEQ, nr0 = r0 - b0i * SEQ;
    int b1i = r1 / SEQ, nr1 = r1 - b1i * SEQ;

#pragma unroll
    for (int nt = 0; nt < 3; nt++) {
        __half* Wc = Wb[nt & 1];
        // prefetch next W tile into the other buffer
        if (nt < 2) {
            __half* Wn = Wb[(nt + 1) & 1];
#pragma unroll
            for (int it = 0; it < 8; it++) {
                int s = tid + it * 256;
                int row = s >> 4, c = s & 15;
                CP_ASYNC16(smem_u32(Wn + row * GSTR + c * 8),
                           g_qkvwh + (size_t)((nt + 1) * 128 + row) * CH + c * 8);
            }
            CP_COMMIT();
        }

        uint32_t wbse = smem_u32(Wc + (wn * 64 + ((tg & 2) ? 8 : 0) + tr) * GSTR + ((tg & 1) ? 8 : 0));
        float acc[8][4] = {};
#pragma unroll
        for (int ks = 0; ks < 8; ks++) {
            uint32_t xf[4];
            ldsm_x4(xf[0], xf[1], xf[2], xf[3], xbse + ks * 32);
#pragma unroll
            for (int jj = 0; jj < 4; jj++) {
                uint32_t wf[4];
                ldsm_x4(wf[0], wf[1], wf[2], wf[3],
                        wbse + (uint32_t)(jj * 16 * GSTR * 2) + ks * 32);
                mma_f16(acc[2 * jj][0], acc[2 * jj][1], acc[2 * jj][2], acc[2 * jj][3],
                        xf[0], xf[1], xf[2], xf[3], wf[0], wf[1]);
                mma_f16(acc[2 * jj + 1][0], acc[2 * jj + 1][1], acc[2 * jj + 1][2], acc[2 * jj + 1][3],
                        xf[0], xf[1], xf[2], xf[3], wf[2], wf[3]);
            }
        }

        __half* dst = (nt == 0) ? g_q : (nt == 1) ? g_k : g_v;
        float sc = (nt == 0) ? (float)QS_LOG2E : 1.0f;
#pragma unroll
        for (int j = 0; j < 8; j++) {
            int cG = wn * 64 + j * 8;
            int h = cG >> 5;
            int dcol = (cG & 31) + 2 * q4;
            *(uint32_t*)(dst + ((size_t)((b0i * NHEAD + h) * SEQ) + nr0) * HD + dcol) =
                pack_h2(acc[j][0] * sc, acc[j][1] * sc);
            *(uint32_t*)(dst + ((size_t)((b1i * NHEAD + h) * SEQ) + nr1) * HD + dcol) =
                pack_h2(acc[j][2] * sc, acc[j][3] * sc);
        }

        if (nt < 2) {
            CP_WAIT0();
            __syncthreads();
        }
    }
}

// ============================================================
// proj GEMM: out[M,128] = ao[M,128] @ projW^T + proj_b
// ============================================================
__global__ void __launch_bounds__(256) gemm_proj(const float* __restrict__ bias,
                                                 float* __restrict__ out) {
    extern __shared__ __half gsm[];
    __half* Xs = gsm;
    __half* Ws = gsm + 64 * GSTR;

    int m0 = blockIdx.x * 64;
    int tid = threadIdx.x, lane = tid & 31, warp = tid >> 5;
    int wm = warp >> 1, wn = warp & 1;
    int grp = lane >> 2, q4 = lane & 3;

#pragma unroll
    for (int s = tid; s < 1024; s += 256) {
        int row = s >> 4, c = s & 15;
        *(uint4*)(Xs + row * GSTR + c * 8) =
            *(const uint4*)(g_ao + (size_t)(m0 + row) * CH + c * 8);
    }
#pragma unroll
    for (int s = tid; s < 2048; s += 256) {
        int row = s >> 4, c = s & 15;
        *(uint4*)(Ws + row * GSTR + c * 8) =
            *(const uint4*)(g_projwh + (size_t)row * CH + c * 8);
    }
    __syncthreads();

    int tg = lane >> 3, tr = lane & 7;
    uint32_t xbse = smem_u32(Xs + (wm * 16 + ((tg & 1) ? 8 : 0) + tr) * GSTR + ((tg & 2) ? 8 : 0));
    uint32_t wbse = smem_u32(Ws + (wn * 64 + ((tg & 2) ? 8 : 0) + tr) * GSTR + ((tg & 1) ? 8 : 0));

    float acc[8][4] = {};
#pragma unroll
    for (int ks = 0; ks < 8; ks++) {
        uint32_t xf[4];
        ldsm_x4(xf[0], xf[1], xf[2], xf[3], xbse + ks * 32);
#pragma unroll
        for (int jj = 0; jj < 4; jj++) {
            uint32_t wf[4];
            ldsm_x4(wf[0], wf[1], wf[2], wf[3],
                    wbse + (uint32_t)(jj * 16 * GSTR * 2) + ks * 32);
            mma_f16(acc[2 * jj][0], acc[2 * jj][1], acc[2 * jj][2], acc[2 * jj][3],
                    xf[0], xf[1], xf[2], xf[3], wf[0], wf[1]);
            mma_f16(acc[2 * jj + 1][0], acc[2 * jj + 1][1], acc[2 * jj + 1][2], acc[2 * jj + 1][3],
                    xf[0], xf[1], xf[2], xf[3], wf[2], wf[3]);
        }
    }

    int r0 = m0 + wm * 16 + grp;
    int r1 = r0 + 8;
#pragma unroll
    for (int j = 0; j < 8; j++) {
        int colb = wn * 64 + j * 8 + 2 * q4;
        float2 pb = *(const float2*)(bias + colb);
        *(float2*)(out + (size_t)r0 * CH + colb) =
            make_float2(acc[j][0] + pb.x, acc[j][1] + pb.y);
        *(float2*)(out + (size_t)r1 * CH + colb) =
            make_float2(acc[j][2] + pb.x, acc[j][3] + pb.y);
    }
}

// ============================================================
// fp16 attention: ldmatrix frags, log2-domain softmax (fp32 ex2),
// scalar rowsum, bias prefetch. One CTA per (b,h), 3 CTAs/SM.
// Tail m-tile (24) assigned per-CTA-hashed warp for SMSP balance.
// ============================================================
#define ATTN_SMEM (KS_ROWS*KSS*2 + HD*VTS*2)   // 58112 B

__global__ void __launch_bounds__(256, 3) attn_mma(const float* __restrict__ mask) {
    extern __shared__ __half sm[];
    __half* Ks = sm;                    // [400][40]
    __half* Vt = sm + KS_ROWS * KSS;    // [32][408]

    int g = blockIdx.x;
    int w = g >> 4;
    int r = g & 15;
    int b = (r >> 2) * NWIN + w;
    int h = r & 3;
    size_t base = ((size_t)(b * NHEAD + h) * SEQ) * HD;

    int tid = threadIdx.x;
    const uint4 z16 = make_uint4(0, 0, 0, 0);
    for (int s = tid; s < KS_ROWS * 4; s += 256) {
        int row = s >> 2, c = s & 3;
        uint4 kv = (row < SEQ) ? *(const uint4*)(g_k + base + (size_t)row * HD + c * 8) : z16;
        *(uint4*)(Ks + row * KSS + c * 8) = kv;
    }
    for (int s = tid; s < SEQ * 16; s += 256) {
        int row = s >> 4, dp = (s & 15) * 2;
        __half2 v2 = *(const __half2*)(g_v + base + (size_t)row * HD + dp);
        Vt[dp * VTS + row] = v2.x;
        Vt[(dp + 1) * VTS + row] = v2.y;
    }
    for (int s = tid; s < HD * 16; s += 256) {
        int d = s >> 4, c = SEQ + (s & 15);
        Vt[d * VTS + c] = __half(0.0f);
    }
    __syncthreads();

    bool domask = (g_mflag[w] != 0);
    int lane = tid & 31, warp = tid >> 5;
    int grp = lane >> 2, q4 = lane & 3;

    int tg = lane >> 3, tr = lane & 7;
    int rsel = (tg & 2) ? 8 : 0;
    int csel = (tg & 1) ? 8 : 0;
    uint32_t kb = smem_u32(Ks + (rsel + tr) * KSS + csel);
    uint32_t vb = smem_u32(Vt + (rsel + tr) * VTS + csel);

    const __half* biasp = g_bias + (size_t)h * NN;
    const float* maskp = mask + (size_t)w * NN;

    // 24 full tiles split 3/warp; tile 24 goes to a per-CTA-hashed warp
    for (int it = 0; it < 4; it++) {
        int mt;
        if (it < 3) mt = warp + it * 8;
        else { if (warp != (g & 7)) break; mt = 24; }

        int m0 = mt * 16;
        int row0 = m0 + grp;
        int row1 = row0 + 8;
        int r1c = (row1 < SEQ) ? row1 : SEQ - 1;

        const __half* q0p = g_q + base + (size_t)row0 * HD;
        const __half* q1p = g_q + base + (size_t)r1c * HD;
        uint32_t aq[2][4];
#pragma unroll
        for (int ks = 0; ks < 2; ks++) {
            aq[ks][0] = *(const uint32_t*)(q0p + ks * 16 + 2 * q4);
            aq[ks][1] = *(const uint32_t*)(q1p + ks * 16 + 2 * q4);
            aq[ks][2] = *(const uint32_t*)(q0p + ks * 16 + 2 * q4 + 8);
            aq[ks][3] = *(const uint32_t*)(q1p + ks * 16 + 2 * q4 + 8);
        }

        const __half* b0r = biasp + (size_t)row0 * SEQ + 2 * q4;
        const __half* b1r = biasp + (size_t)r1c * SEQ + 2 * q4;
        const float* m0r = maskp + (size_t)row0 * SEQ + 2 * q4;
        const float* m1r = maskp + (size_t)r1c * SEQ + 2 * q4;

        float oacc[4][4] = {};
        float rs0 = 0.0f, rs1 = 0.0f;

        uint32_t pb0 = *(const uint32_t*)(b0r);
        uint32_t pb1 = *(const uint32_t*)(b1r);
        uint32_t pb2 = *(const uint32_t*)(b0r + 8);
        uint32_t pb3 = *(const uint32_t*)(b1r + 8);

        for (int nt = 0; nt < NT16; nt++) {
            int n0 = nt * 16;
            bool tail = (nt == NT16 - 1);

            uint32_t kf0[4], kf1[4];
            uint32_t kaddr = kb + (uint32_t)(n0 * (KSS * 2));
            ldsm_x4(kf0[0], kf0[1], kf0[2], kf0[3], kaddr);
            ldsm_x4(kf1[0], kf1[1], kf1[2], kf1[3], kaddr + 32);

            uint32_t nb0 = 0, nb1 = 0, nb2 = 0, nb3 = 0;
            if (!tail) {
                int nn = n0 + 16;
                nb0 = *(const uint32_t*)(b0r + nn);
                nb1 = *(const uint32_t*)(b1r + nn);
                nb2 = *(const uint32_t*)(b0r + nn + 8);
                nb3 = *(const uint32_t*)(b1r + nn + 8);
            }

            float cL0 = 0.f, cL1 = 0.f, cL2 = 0.f, cL3 = 0.f;
            float cR0 = 0.f, cR1 = 0.f, cR2 = 0.f, cR3 = 0.f;
            mma_f16(cL0, cL1, cL2, cL3, aq[0][0], aq[0][1], aq[0][2], aq[0][3], kf0[0], kf0[1]);
            mma_f16(cR0, cR1, cR2, cR3, aq[0][0], aq[0][1], aq[0][2], aq[0][3], kf0[2], kf0[3]);
            mma_f16(cL0, cL1, cL2, cL3, aq[1][0], aq[1][1], aq[1][2], aq[1][3], kf1[0], kf1[1]);
            mma_f16(cR0, cR1, cR2, cR3, aq[1][0], aq[1][1], aq[1][2], aq[1][3], kf1[2], kf1[3]);

            float2 bL0f = __half22float2(*reinterpret_cast<__half2*>(&pb0));
            float2 bL1f = __half22float2(*reinterpret_cast<__half2*>(&pb1));
            if (domask) {
                float2 mm0 = *(const float2*)(m0r + n0);
                float2 mm1 = *(const float2*)(m1r + n0);
                bL0f.x += mm0.x * LOG2E; bL0f.y += mm0.y * LOG2E;
                bL1f.x += mm1.x * LOG2E; bL1f.y += mm1.y * LOG2E;
            }
            float eL0 = ex2f(cL0 + bL0f.x), eL1 = ex2f(cL1 + bL0f.y);
            float eL2 = ex2f(cL2 + bL1f.x), eL3 = ex2f(cL3 + bL1f.y);

            float eR0 = 0.f, eR1 = 0.f, eR2 = 0.f, eR3 = 0.f;
            if (!tail) {
                float2 bR0f = __half22float2(*reinterpret_cast<__half2*>(&pb2));
                float2 bR1f = __half22float2(*reinterpret_cast<__half2*>(&pb3));
                if (domask) {
                    float2 mm0 = *(const float2*)(m0r + n0 + 8);
                    float2 mm1 = *(const float2*)(m1r + n0 + 8);
                    bR0f.x += mm0.x * LOG2E; bR0f.y += mm0.y * LOG2E;
                    bR1f.x += mm1.x * LOG2E; bR1f.y += mm1.y * LOG2E;
                }
                eR0 = ex2f(cR0 + bR0f.x); eR1 = ex2f(cR1 + bR0f.y);
                eR2 = ex2f(cR2 + bR1f.x); eR3 = ex2f(cR3 + bR1f.y);
            }

            rs0 += (eL0 + eL1) + (eR0 + eR1);
            rs1 += (eL2 + eL3) + (eR2 + eR3);

            uint32_t ap0 = pack_h2(eL0, eL1);
            uint32_t ap1 = pack_h2(eL2, eL3);
            uint32_t ap2 = pack_h2(eR0, eR1);
            uint32_t ap3 = pack_h2(eR2, eR3);

            uint32_t vf0[4], vf1[4];
            uint32_t vaddr = vb + (uint32_t)(n0 * 2);
            ldsm_x4(vf0[0], vf0[1], vf0[2], vf0[3], vaddr);
            ldsm_x4(vf1[0], vf1[1], vf1[2], vf1[3], vaddr + 16 * VTS * 2);
            mma_f16(oacc[0][0], oacc[0][1], oacc[0][2], oacc[0][3], ap0, ap1, ap2, ap3, vf0[0], vf0[1]);
            mma_f16(oacc[1][0], oacc[1][1], oacc[1][2], oacc[1][3], ap0, ap1, ap2, ap3, vf0[2], vf0[3]);
            mma_f16(oacc[2][0], oacc[2][1], oacc[2][2], oacc[2][3], ap0, ap1, ap2, ap3, vf1[0], vf1[1]);
            mma_f16(oacc[3][0], oacc[3][1], oacc[3][2], oacc[3][3], ap0, ap1, ap2, ap3, vf1[2], vf1[3]);

            pb0 = nb0; pb1 = nb1; pb2 = nb2; pb3 = nb3;
        }

        rs0 += __shfl_xor_sync(0xffffffffu, rs0, 1);
        rs0 += __shfl_xor_sync(0xffffffffu, rs0, 2);
        rs1 += __shfl_xor_sync(0xffffffffu, rs1, 1);
        rs1 += __shfl_xor_sync(0xffffffffu, rs1, 2);
        float inv0 = __frcp_rn(rs0), inv1 = __frcp_rn(rs1);

        {
            __half* op = g_ao + ((size_t)b * SEQ + row0) * CH + h * HD + 2 * q4;
#pragma unroll
            for (int j = 0; j < 4; j++)
                *(uint32_t*)(op + j * 8) = pack_h2(oacc[j][0] * inv0, oacc[j][1] * inv0);
        }
        if (row1 < SEQ) {
            __half* op = g_ao + ((size_t)b * SEQ + row1) * CH + h * HD + 2 * q4;
#pragma unroll
            for (int j = 0; j < 4; j++)
                *(uint32_t*)(op + j * 8) = pack_h2(oacc[j][2] * inv1, oacc[j][3] * inv1);
        }
    }
}

// ============================================================
extern "C" void kernel_launch(void* const* d_in, const int* in_sizes, int n_in,
                              void* d_out, int out_size) {
    (void)in_sizes; (void)n_in; (void)out_size;
    const float* x          = (const float*)d_in[0];
    const float* mask       = (const float*)d_in[1];
    const float* qkv_w      = (const float*)d_in[2];
    const float* proj_w     = (const float*)d_in[3];
    const float* proj_b     = (const float*)d_in[4];
    const float* bias_table = (const float*)d_in[5];
    const int*   rel_index  = (const int*)d_in[6];
    float* out = (float*)d_out;

    cudaFuncSetAttribute(attn_mma, cudaFuncAttributeMaxDynamicSharedMemorySize, ATTN_SMEM);
    cudaFuncSetAttribute(gemm_qkv, cudaFuncAttributeMaxDynamicSharedMemorySize, GSMEM_QKV);
    cudaFuncSetAttribute(gemm_proj, cudaFuncAttributeMaxDynamicSharedMemorySize, GSMEM_PRJ);

    convert_w_kernel<<<((384 * CH + CH * CH) / 8 + 255) / 256, 256>>>(qkv_w, proj_w);
    bias_gather_kernel<<<(NN + 255) / 256, 256>>>(bias_table, rel_index);
    maskflag_kernel<<<dim3(NWIN, 32), 256>>>(mask);
    gemm_qkv<<<MROWS / 64, 256, GSMEM_QKV>>>(x);
    attn_mma<<<B_TOT * NHEAD, 256, ATTN_SMEM>>>(mask);
    gemm_proj<<<MROWS / 64, 256, GSMEM_PRJ>>>(proj_b, out);
}

// round 16
// speedup vs baseline: 1.0533x; 1.0533x over previous
#include <cuda_runtime.h>
#include <cuda_fp16.h>
#include <cstdint>
#include <math.h>

#define B_TOT 512
#define SEQ   392
#define CH    128
#define NHEAD 4
#define HD    32
#define NWIN  128
#define MROWS 200704               // B_TOT*SEQ
#define NN    (SEQ*SEQ)            // 153664
#define QKV_SCALE 0.17677669529663687f
#define LOG2E 1.4426950408889634f
#define QS_LOG2E (QKV_SCALE*LOG2E)

#define MT    25                   // ceil(392/16) m-tiles
#define NT16  25                   // 24 full 16-col tiles + tail (8 cols)
#define KSS   40                   // K smem stride (halves)
#define KS_ROWS 400
#define VTS   408                  // V^T smem stride (halves)
#define GSTR  136                  // gemm smem stride (halves)
#define GSMEM_QKV ((64 + 2*128) * GSTR * 2)   // X + double-buffered W = 87040 B
#define GSMEM_PRJ ((64 + 128) * GSTR * 2)     // 52224 B

// -------- scratch (device globals: no allocations allowed) --------
__device__ __half g_qkvwh[384*CH];
__device__ __half g_projwh[CH*CH];
__device__ __half g_q[(size_t)B_TOT*NHEAD*SEQ*HD];
__device__ __half g_k[(size_t)B_TOT*NHEAD*SEQ*HD];
__device__ __half g_v[(size_t)B_TOT*NHEAD*SEQ*HD];
__device__ __half g_ao[(size_t)MROWS*CH];
__device__ __half g_bias[(size_t)NHEAD*NN + 64];  // fp16, pre-scaled by log2e
__device__ int    g_mflag[NWIN];

// ============================================================
__device__ __forceinline__ uint32_t pack_h2(float lo, float hi) {
    uint32_t r;
    asm("cvt.rn.f16x2.f32 %0, %1, %2;" : "=r"(r) : "f"(hi), "f"(lo));
    return r;
}
__device__ __forceinline__ float ex2f(float x) {
    float y;
    asm("ex2.approx.f32 %0, %1;" : "=f"(y) : "f"(x));
    return y;
}
__device__ __forceinline__ uint32_t smem_u32(const void* p) {
    uint32_t a;
    asm("{ .reg .u64 t; cvta.to.shared.u64 t, %1; cvt.u32.u64 %0, t; }" : "=r"(a) : "l"(p));
    return a;
}
__device__ __forceinline__ void mma_f16(float& d0, float& d1, float& d2, float& d3,
                                        uint32_t a0, uint32_t a1, uint32_t a2, uint32_t a3,
                                        uint32_t b0, uint32_t b1) {
    asm volatile("mma.sync.aligned.m16n8k16.row.col.f32.f16.f16.f32 "
                 "{%0,%1,%2,%3}, {%4,%5,%6,%7}, {%8,%9}, {%0,%1,%2,%3};"
                 : "+f"(d0), "+f"(d1), "+f"(d2), "+f"(d3)
                 : "r"(a0), "r"(a1), "r"(a2), "r"(a3), "r"(b0), "r"(b1));
}
__device__ __forceinline__ void ldsm_x4(uint32_t& r0, uint32_t& r1, uint32_t& r2, uint32_t& r3,
                                        uint32_t addr) {
    asm volatile("ldmatrix.sync.aligned.m8n8.x4.shared.b16 {%0,%1,%2,%3}, [%4];"
                 : "=r"(r0), "=r"(r1), "=r"(r2), "=r"(r3) : "r"(addr));
}
#define CP_ASYNC16(sa, gp) \
    asm volatile("cp.async.ca.shared.global [%0], [%1], 16;" :: "r"(sa), "l"(gp) : "memory")
#define CP_COMMIT() asm volatile("cp.async.commit_group;" ::: "memory")
#define CP_WAIT0()  asm volatile("cp.async.wait_group 0;" ::: "memory")

// ============================================================
// Prep kernels
// ============================================================
__global__ void convert_w_kernel(const float* __restrict__ qkv_w,
                                 const float* __restrict__ proj_w) {
    if (blockIdx.x == 0 && threadIdx.x < NWIN) g_mflag[threadIdx.x] = 0;
    int t = blockIdx.x * 256 + threadIdx.x;   // 8 elems/thread
    const int QN = 384 * CH / 8;              // 6144
    const float* src; __half* dst; int i;
    if (t < QN) { src = qkv_w; dst = g_qkvwh; i = t; }
    else { src = proj_w; dst = g_projwh; i = t - QN; if (i >= CH * CH / 8) return; }
    float4 a = *(const float4*)(src + i * 8);
    float4 b = *(const float4*)(src + i * 8 + 4);
    uint4 o;
    o.x = pack_h2(a.x, a.y); o.y = pack_h2(a.z, a.w);
    o.z = pack_h2(b.x, b.y); o.w = pack_h2(b.z, b.w);
    *(uint4*)(dst + i * 8) = o;
}
__global__ void bias_gather_kernel(const float* __restrict__ table,
                                   const int* __restrict__ ridx) {
    int t = blockIdx.x * 256 + threadIdx.x;
    if (t >= NN) return;
    int r = ridx[t];
    float4 tv = *(const float4*)(table + (size_t)r * 4);
    g_bias[0 * (size_t)NN + t] = __float2half(tv.x * LOG2E);
    g_bias[1 * (size_t)NN + t] = __float2half(tv.y * LOG2E);
    g_bias[2 * (size_t)NN + t] = __float2half(tv.z * LOG2E);
    g_bias[3 * (size_t)NN + t] = __float2half(tv.w * LOG2E);
}
// grid (NWIN, 8)
__global__ void maskflag_kernel(const float* __restrict__ mask) {
    int w = blockIdx.x;
    int slice = blockIdx.y;
    const int SL = NN / 8;                    // 19208
    const float* mp = mask + (size_t)w * NN + (size_t)slice * SL;
    int any = 0;
    for (int i = threadIdx.x; i < SL; i += 256)
        any |= (mp[i] != 0.0f);
    any = __syncthreads_or(any);
    if (threadIdx.x == 0 && any) atomicOr(&g_mflag[w], 1);
}

// ============================================================
// Fused qkv GEMM (R15's cp.async version, measured 101us):
// fp32 x read once (convert while staging); 3 qkv column-tiles
// looped in-kernel with cp.async double-buffered W staging.
// ============================================================
__global__ void __launch_bounds__(256) gemm_qkv(const float* __restrict__ x) {
    extern __shared__ __half gsm[];
    __half* Xs = gsm;                         // [64][GSTR]
    __half* Wb[2] = { gsm + 64 * GSTR, gsm + (64 + 128) * GSTR };

    int m0 = blockIdx.x * 64;
    int tid = threadIdx.x, lane = tid & 31, warp = tid >> 5;
    int wm = warp >> 1, wn = warp & 1;
    int grp = lane >> 2, q4 = lane & 3;

    // ---- issue cp.async for W tile 0 ----
#pragma unroll
    for (int it = 0; it < 8; it++) {
        int s = tid + it * 256;
        int row = s >> 4, c = s & 15;
        CP_ASYNC16(smem_u32(Wb[0] + row * GSTR + c * 8),
                   g_qkvwh + (size_t)row * CH + c * 8);
    }
    CP_COMMIT();

    // ---- stage X (fp32 -> fp16) meanwhile ----
#pragma unroll
    for (int s = tid; s < 2048; s += 256) {
        int row = s >> 5, c = s & 31;
        float4 xv = *(const float4*)(x + (size_t)(m0 + row) * CH + c * 4);
        uint2 p;
        p.x = pack_h2(xv.x, xv.y);
        p.y = pack_h2(xv.z, xv.w);
        *(uint2*)(Xs + row * GSTR + c * 4) = p;
    }
    CP_WAIT0();
    __syncthreads();

    int tg = lane >> 3, tr = lane & 7;
    uint32_t xbse = smem_u32(Xs + (wm * 16 + ((tg & 1) ? 8 : 0) + tr) * GSTR + ((tg & 2) ? 8 : 0));

    int r0 = m0 + wm * 16 + grp;
    int r1 = r0 + 8;
    int b0i = r0 / SEQ, nr0 = r0 - b0i * SEQ;
    int b1i = r1 / SEQ, nr1 = r1 - b1i * SEQ;

#pragma unroll
    for (int nt = 0; nt < 3; nt++) {
        __half* Wc = Wb[nt & 1];
        if (nt < 2) {
            __half* Wn = Wb[(nt + 1) & 1];
#pragma unroll
            for (int it = 0; it < 8; it++) {
                int s = tid + it * 256;
                int row = s >> 4, c = s & 15;
                CP_ASYNC16(smem_u32(Wn + row * GSTR + c * 8),
                           g_qkvwh + (size_t)((nt + 1) * 128 + row) * CH + c * 8);
            }
            CP_COMMIT();
        }

        uint32_t wbse = smem_u32(Wc + (wn * 64 + ((tg & 2) ? 8 : 0) + tr) * GSTR + ((tg & 1) ? 8 : 0));
        float acc[8][4] = {};
#pragma unroll
        for (int ks = 0; ks < 8; ks++) {
            uint32_t xf[4];
            ldsm_x4(xf[0], xf[1], xf[2], xf[3], xbse + ks * 32);
#pragma unroll
            for (int jj = 0; jj < 4; jj++) {
                uint32_t wf[4];
                ldsm_x4(wf[0], wf[1], wf[2], wf[3],
                        wbse + (uint32_t)(jj * 16 * GSTR * 2) + ks * 32);
                mma_f16(acc[2 * jj][0], acc[2 * jj][1], acc[2 * jj][2], acc[2 * jj][3],
                        xf[0], xf[1], xf[2], xf[3], wf[0], wf[1]);
                mma_f16(acc[2 * jj + 1][0], acc[2 * jj + 1][1], acc[2 * jj + 1][2], acc[2 * jj + 1][3],
                        xf[0], xf[1], xf[2], xf[3], wf[2], wf[3]);
            }
        }

        __half* dst = (nt == 0) ? g_q : (nt == 1) ? g_k : g_v;
        float sc = (nt == 0) ? (float)QS_LOG2E : 1.0f;
#pragma unroll
        for (int j = 0; j < 8; j++) {
            int cG = wn * 64 + j * 8;
            int h = cG >> 5;
            int dcol = (cG & 31) + 2 * q4;
            *(uint32_t*)(dst + ((size_t)((b0i * NHEAD + h) * SEQ) + nr0) * HD + dcol) =
                pack_h2(acc[j][0] * sc, acc[j][1] * sc);
            *(uint32_t*)(dst + ((size_t)((b1i * NHEAD + h) * SEQ) + nr1) * HD + dcol) =
                pack_h2(acc[j][2] * sc, acc[j][3] * sc);
        }

        if (nt < 2) {
            CP_WAIT0();
            __syncthreads();
        }
    }
}

// ============================================================
// proj GEMM: out[M,128] = ao[M,128] @ projW^T + proj_b
// ============================================================
__global__ void __launch_bounds__(256) gemm_proj(const float* __restrict__ bias,
                                                 float* __restrict__ out) {
    extern __shared__ __half gsm[];
    __half* Xs = gsm;
    __half* Ws = gsm + 64 * GSTR;

    int m0 = blockIdx.x * 64;
    int tid = threadIdx.x, lane = tid & 31, warp = tid >> 5;
    int wm = warp >> 1, wn = warp & 1;
    int grp = lane >> 2, q4 = lane & 3;

#pragma unroll
    for (int s = tid; s < 1024; s += 256) {
        int row = s >> 4, c = s & 15;
        *(uint4*)(Xs + row * GSTR + c * 8) =
            *(const uint4*)(g_ao + (size_t)(m0 + row) * CH + c * 8);
    }
#pragma unroll
    for (int s = tid; s < 2048; s += 256) {
        int row = s >> 4, c = s & 15;
        *(uint4*)(Ws + row * GSTR + c * 8) =
            *(const uint4*)(g_projwh + (size_t)row * CH + c * 8);
    }
    __syncthreads();

    int tg = lane >> 3, tr = lane & 7;
    uint32_t xbse = smem_u32(Xs + (wm * 16 + ((tg & 1) ? 8 : 0) + tr) * GSTR + ((tg & 2) ? 8 : 0));
    uint32_t wbse = smem_u32(Ws + (wn * 64 + ((tg & 2) ? 8 : 0) + tr) * GSTR + ((tg & 1) ? 8 : 0));

    float acc[8][4] = {};
#pragma unroll
    for (int ks = 0; ks < 8; ks++) {
        uint32_t xf[4];
        ldsm_x4(xf[0], xf[1], xf[2], xf[3], xbse + ks * 32);
#pragma unroll
        for (int jj = 0; jj < 4; jj++) {
            uint32_t wf[4];
            ldsm_x4(wf[0], wf[1], wf[2], wf[3],
                    wbse + (uint32_t)(jj * 16 * GSTR * 2) + ks * 32);
            mma_f16(acc[2 * jj][0], acc[2 * jj][1], acc[2 * jj][2], acc[2 * jj][3],
                    xf[0], xf[1], xf[2], xf[3], wf[0], wf[1]);
            mma_f16(acc[2 * jj + 1][0], acc[2 * jj + 1][1], acc[2 * jj + 1][2], acc[2 * jj + 1][3],
                    xf[0], xf[1], xf[2], xf[3], wf[2], wf[3]);
        }
    }

    int r0 = m0 + wm * 16 + grp;
    int r1 = r0 + 8;
#pragma unroll
    for (int j = 0; j < 8; j++) {
        int colb = wn * 64 + j * 8 + 2 * q4;
        float2 pb = *(const float2*)(bias + colb);
        *(float2*)(out + (size_t)r0 * CH + colb) =
            make_float2(acc[j][0] + pb.x, acc[j][1] + pb.y);
        *(float2*)(out + (size_t)r1 * CH + colb) =
            make_float2(acc[j][2] + pb.x, acc[j][3] + pb.y);
    }
}

// ============================================================
// fp16 attention — VERBATIM R14 (measured-good): ldmatrix frags,
// log2-domain softmax (fp32 ex2), scalar rowsum, bias prefetch.
// One CTA per (b,h), 8 warps, 3 CTAs/SM.
// ============================================================
#define ATTN_SMEM (KS_ROWS*KSS*2 + HD*VTS*2)   // 58112 B

__global__ void __launch_bounds__(256, 3) attn_mma(const float* __restrict__ mask) {
    extern __shared__ __half sm[];
    __half* Ks = sm;                    // [400][40]
    __half* Vt = sm + KS_ROWS * KSS;    // [32][408]

    int g = blockIdx.x;
    int w = g >> 4;
    int r = g & 15;
    int b = (r >> 2) * NWIN + w;
    int h = r & 3;
    size_t base = ((size_t)(b * NHEAD + h) * SEQ) * HD;

    int tid = threadIdx.x;
    const uint4 z16 = make_uint4(0, 0, 0, 0);
    for (int s = tid; s < KS_ROWS * 4; s += 256) {
        int row = s >> 2, c = s & 3;
        uint4 kv = (row < SEQ) ? *(const uint4*)(g_k + base + (size_t)row * HD + c * 8) : z16;
        *(uint4*)(Ks + row * KSS + c * 8) = kv;
    }
    for (int s = tid; s < SEQ * 16; s += 256) {
        int row = s >> 4, dp = (s & 15) * 2;
        __half2 v2 = *(const __half2*)(g_v + base + (size_t)row * HD + dp);
        Vt[dp * VTS + row] = v2.x;
        Vt[(dp + 1) * VTS + row] = v2.y;
    }
    for (int s = tid; s < HD * 16; s += 256) {
        int d = s >> 4, c = SEQ + (s & 15);
        Vt[d * VTS + c] = __half(0.0f);
    }
    __syncthreads();

    bool domask = (g_mflag[w] != 0);
    int lane = tid & 31, warp = tid >> 5;
    int grp = lane >> 2, q4 = lane & 3;

    int tg = lane >> 3, tr = lane & 7;
    int rsel = (tg & 2) ? 8 : 0;
    int csel = (tg & 1) ? 8 : 0;
    uint32_t kb = smem_u32(Ks + (rsel + tr) * KSS + csel);
    uint32_t vb = smem_u32(Vt + (rsel + tr) * VTS + csel);

    const __half* biasp = g_bias + (size_t)h * NN;
    const float* maskp = mask + (size_t)w * NN;

    for (int mt = warp; mt < MT; mt += 8) {
        int m0 = mt * 16;
        int row0 = m0 + grp;
        int row1 = row0 + 8;
        int r1c = (row1 < SEQ) ? row1 : SEQ - 1;

        const __half* q0p = g_q + base + (size_t)row0 * HD;
        const __half* q1p = g_q + base + (size_t)r1c * HD;
        uint32_t aq[2][4];
#pragma unroll
        for (int ks = 0; ks < 2; ks++) {
            aq[ks][0] = *(const uint32_t*)(q0p + ks * 16 + 2 * q4);
            aq[ks][1] = *(const uint32_t*)(q1p + ks * 16 + 2 * q4);
            aq[ks][2] = *(const uint32_t*)(q0p + ks * 16 + 2 * q4 + 8);
            aq[ks][3] = *(const uint32_t*)(q1p + ks * 16 + 2 * q4 + 8);
        }

        const __half* b0r = biasp + (size_t)row0 * SEQ + 2 * q4;
        const __half* b1r = biasp + (size_t)r1c * SEQ + 2 * q4;
        const float* m0r = maskp + (size_t)row0 * SEQ + 2 * q4;
        const float* m1r = maskp + (size_t)r1c * SEQ + 2 * q4;

        float oacc[4][4] = {};
        float rs0 = 0.0f, rs1 = 0.0f;

        uint32_t pb0 = *(const uint32_t*)(b0r);
        uint32_t pb1 = *(const uint32_t*)(b1r);
        uint32_t pb2 = *(const uint32_t*)(b0r + 8);
        uint32_t pb3 = *(const uint32_t*)(b1r + 8);

        for (int nt = 0; nt < NT16; nt++) {
            int n0 = nt * 16;
            bool tail = (nt == NT16 - 1);

            uint32_t kf0[4], kf1[4];
            uint32_t kaddr = kb + (uint32_t)(n0 * (KSS * 2));
            ldsm_x4(kf0[0], kf0[1], kf0[2], kf0[3], kaddr);
            ldsm_x4(kf1[0], kf1[1], kf1[2], kf1[3], kaddr + 32);

            uint32_t nb0 = 0, nb1 = 0, nb2 = 0, nb3 = 0;
            if (!tail) {
                int nn = n0 + 16;
                nb0 = *(const uint32_t*)(b0r + nn);
                nb1 = *(const uint32_t*)(b1r + nn);
                nb2 = *(const uint32_t*)(b0r + nn + 8);
                nb3 = *(const uint32_t*)(b1r + nn + 8);
            }

            float cL0 = 0.f, cL1 = 0.f, cL2 = 0.f, cL3 = 0.f;
            float cR0 = 0.f, cR1 = 0.f, cR2 = 0.f, cR3 = 0.f;
            mma_f16(cL0, cL1, cL2, cL3, aq[0][0], aq[0][1], aq[0][2], aq[0][3], kf0[0], kf0[1]);
            mma_f16(cR0, cR1, cR2, cR3, aq[0][0], aq[0][1], aq[0][2], aq[0][3], kf0[2], kf0[3]);
            mma_f16(cL0, cL1, cL2, cL3, aq[1][0], aq[1][1], aq[1][2], aq[1][3], kf1[0], kf1[1]);
            mma_f16(cR0, cR1, cR2, cR3, aq[1][0], aq[1][1], aq[1][2], aq[1][3], kf1[2], kf1[3]);

            float2 bL0f = __half22float2(*reinterpret_cast<__half2*>(&pb0));
            float2 bL1f = __half22float2(*reinterpret_cast<__half2*>(&pb1));
            if (domask) {
                float2 mm0 = *(const float2*)(m0r + n0);
                float2 mm1 = *(const float2*)(m1r + n0);
                bL0f.x += mm0.x * LOG2E; bL0f.y += mm0.y * LOG2E;
                bL1f.x += mm1.x * LOG2E; bL1f.y += mm1.y * LOG2E;
            }
            float eL0 = ex2f(cL0 + bL0f.x), eL1 = ex2f(cL1 + bL0f.y);
            float eL2 = ex2f(cL2 + bL1f.x), eL3 = ex2f(cL3 + bL1f.y);

            float eR0 = 0.f, eR1 = 0.f, eR2 = 0.f, eR3 = 0.f;
            if (!tail) {
                float2 bR0f = __half22float2(*reinterpret_cast<__half2*>(&pb2));
                float2 bR1f = __half22float2(*reinterpret_cast<__half2*>(&pb3));
                if (domask) {
                    float2 mm0 = *(const float2*)(m0r + n0 + 8);
                    float2 mm1 = *(const float2*)(m1r + n0 + 8);
                    bR0f.x += mm0.x * LOG2E; bR0f.y += mm0.y * LOG2E;
                    bR1f.x += mm1.x * LOG2E; bR1f.y += mm1.y * LOG2E;
                }
                eR0 = ex2f(cR0 + bR0f.x); eR1 = ex2f(cR1 + bR0f.y);
                eR2 = ex2f(cR2 + bR1f.x); eR3 = ex2f(cR3 + bR1f.y);
            }

            rs0 += (eL0 + eL1) + (eR0 + eR1);
            rs1 += (eL2 + eL3) + (eR2 + eR3);

            uint32_t ap0 = pack_h2(eL0, eL1);
            uint32_t ap1 = pack_h2(eL2, eL3);
            uint32_t ap2 = pack_h2(eR0, eR1);
            uint32_t ap3 = pack_h2(eR2, eR3);

            uint32_t vf0[4], vf1[4];
            uint32_t vaddr = vb + (uint32_t)(n0 * 2);
            ldsm_x4(vf0[0], vf0[1], vf0[2], vf0[3], vaddr);
            ldsm_x4(vf1[0], vf1[1], vf1[2], vf1[3], vaddr + 16 * VTS * 2);
            mma_f16(oacc[0][0], oacc[0][1], oacc[0][2], oacc[0][3], ap0, ap1, ap2, ap3, vf0[0], vf0[1]);
            mma_f16(oacc[1][0], oacc[1][1], oacc[1][2], oacc[1][3], ap0, ap1, ap2, ap3, vf0[2], vf0[3]);
            mma_f16(oacc[2][0], oacc[2][1], oacc[2][2], oacc[2][3], ap0, ap1, ap2, ap3, vf1[0], vf1[1]);
            mma_f16(oacc[3][0], oacc[3][1], oacc[3][2], oacc[3][3], ap0, ap1, ap2, ap3, vf1[2], vf1[3]);

            pb0 = nb0; pb1 = nb1; pb2 = nb2; pb3 = nb3;
        }

        rs0 += __shfl_xor_sync(0xffffffffu, rs0, 1);
        rs0 += __shfl_xor_sync(0xffffffffu, rs0, 2);
        rs1 += __shfl_xor_sync(0xffffffffu, rs1, 1);
        rs1 += __shfl_xor_sync(0xffffffffu, rs1, 2);
        float inv0 = __frcp_rn(rs0), inv1 = __frcp_rn(rs1);

        {
            __half* op = g_ao + ((size_t)b * SEQ + row0) * CH + h * HD + 2 * q4;
#pragma unroll
            for (int j = 0; j < 4; j++)
                *(uint32_t*)(op + j * 8) = pack_h2(oacc[j][0] * inv0, oacc[j][1] * inv0);
        }
        if (row1 < SEQ) {
            __half* op = g_ao + ((size_t)b * SEQ + row1) * CH + h * HD + 2 * q4;
#pragma unroll
            for (int j = 0; j < 4; j++)
                *(uint32_t*)(op + j * 8) = pack_h2(oacc[j][2] * inv1, oacc[j][3] * inv1);
        }
    }
}

// ============================================================
extern "C" void kernel_launch(void* const* d_in, const int* in_sizes, int n_in,
                              void* d_out, int out_size) {
    (void)in_sizes; (void)n_in; (void)out_size;
    const float* x          = (const float*)d_in[0];
    const float* mask       = (const float*)d_in[1];
    const float* qkv_w      = (const float*)d_in[2];
    const float* proj_w     = (const float*)d_in[3];
    const float* proj_b     = (const float*)d_in[4];
    const float* bias_table = (const float*)d_in[5];
    const int*   rel_index  = (const int*)d_in[6];
    float* out = (float*)d_out;

    cudaFuncSetAttribute(attn_mma, cudaFuncAttributeMaxDynamicSharedMemorySize, ATTN_SMEM);
    cudaFuncSetAttribute(gemm_qkv, cudaFuncAttributeMaxDynamicSharedMemorySize, GSMEM_QKV);
    cudaFuncSetAttribute(gemm_proj, cudaFuncAttributeMaxDynamicSharedMemorySize, GSMEM_PRJ);

    convert_w_kernel<<<((384 * CH + CH * CH) / 8 + 255) / 256, 256>>>(qkv_w, proj_w);
    bias_gather_kernel<<<(NN + 255) / 256, 256>>>(bias_table, rel_index);
    maskflag_kernel<<<dim3(NWIN, 8), 256>>>(mask);
    gemm_qkv<<<MROWS / 64, 256, GSMEM_QKV>>>(x);
    attn_mma<<<B_TOT * NHEAD, 256, ATTN_SMEM>>>(mask);
    gemm_proj<<<MROWS / 64, 256, GSMEM_PRJ>>>(proj_b, out);
}

// round 17
// speedup vs baseline: 1.0537x; 1.0004x over previous
#include <cuda_runtime.h>
#include <cuda_fp16.h>
#include <cstdint>
#include <math.h>

#define B_TOT 512
#define SEQ   392
#define CH    128
#define NHEAD 4
#define HD    32
#define NWIN  128
#define MROWS 200704               // B_TOT*SEQ
#define NN    (SEQ*SEQ)            // 153664
#define QKV_SCALE 0.17677669529663687f
#define LOG2E 1.4426950408889634f
#define QS_LOG2E (QKV_SCALE*LOG2E)

#define MT    25                   // ceil(392/16) m-tiles
#define NT16  25                   // 24 full 16-col tiles + tail (8 cols)
#define KSS   40                   // K smem stride (halves)
#define KS_ROWS 400
#define VTS   408                  // V^T smem stride (halves)
#define GSTR  136                  // gemm smem stride (halves)
#define GSMEM_QKV ((128 + 2*128) * GSTR * 2)  // X(128 rows) + 2x W = 104448 B
#define GSMEM_PRJ ((64 + 128) * GSTR * 2)     // 52224 B

// -------- scratch (device globals: no allocations allowed) --------
__device__ __half g_qkvwh[384*CH];
__device__ __half g_projwh[CH*CH];
__device__ __half g_q[(size_t)B_TOT*NHEAD*SEQ*HD];
__device__ __half g_k[(size_t)B_TOT*NHEAD*SEQ*HD];
__device__ __half g_v[(size_t)B_TOT*NHEAD*SEQ*HD];
__device__ __half g_ao[(size_t)MROWS*CH];
__device__ __half g_bias[(size_t)NHEAD*NN + 64];  // fp16, pre-scaled by log2e
__device__ int    g_mflag[NWIN];

// ============================================================
__device__ __forceinline__ uint32_t pack_h2(float lo, float hi) {
    uint32_t r;
    asm("cvt.rn.f16x2.f32 %0, %1, %2;" : "=r"(r) : "f"(hi), "f"(lo));
    return r;
}
__device__ __forceinline__ float ex2f(float x) {
    float y;
    asm("ex2.approx.f32 %0, %1;" : "=f"(y) : "f"(x));
    return y;
}
__device__ __forceinline__ uint32_t smem_u32(const void* p) {
    uint32_t a;
    asm("{ .reg .u64 t; cvta.to.shared.u64 t, %1; cvt.u32.u64 %0, t; }" : "=r"(a) : "l"(p));
    return a;
}
__device__ __forceinline__ void mma_f16(float& d0, float& d1, float& d2, float& d3,
                                        uint32_t a0, uint32_t a1, uint32_t a2, uint32_t a3,
                                        uint32_t b0, uint32_t b1) {
    asm volatile("mma.sync.aligned.m16n8k16.row.col.f32.f16.f16.f32 "
                 "{%0,%1,%2,%3}, {%4,%5,%6,%7}, {%8,%9}, {%0,%1,%2,%3};"
                 : "+f"(d0), "+f"(d1), "+f"(d2), "+f"(d3)
                 : "r"(a0), "r"(a1), "r"(a2), "r"(a3), "r"(b0), "r"(b1));
}
__device__ __forceinline__ void ldsm_x4(uint32_t& r0, uint32_t& r1, uint32_t& r2, uint32_t& r3,
                                        uint32_t addr) {
    asm volatile("ldmatrix.sync.aligned.m8n8.x4.shared.b16 {%0,%1,%2,%3}, [%4];"
                 : "=r"(r0), "=r"(r1), "=r"(r2), "=r"(r3) : "r"(addr));
}
#define CP_ASYNC16(sa, gp) \
    asm volatile("cp.async.ca.shared.global [%0], [%1], 16;" :: "r"(sa), "l"(gp) : "memory")
#define CP_COMMIT() asm volatile("cp.async.commit_group;" ::: "memory")
#define CP_WAIT0()  asm volatile("cp.async.wait_group 0;" ::: "memory")

// ============================================================
// Prep kernels
// ============================================================
__global__ void convert_w_kernel(const float* __restrict__ qkv_w,
                                 const float* __restrict__ proj_w) {
    if (blockIdx.x == 0 && threadIdx.x < NWIN) g_mflag[threadIdx.x] = 0;
    int t = blockIdx.x * 256 + threadIdx.x;   // 8 elems/thread
    const int QN = 384 * CH / 8;              // 6144
    const float* src; __half* dst; int i;
    if (t < QN) { src = qkv_w; dst = g_qkvwh; i = t; }
    else { src = proj_w; dst = g_projwh; i = t - QN; if (i >= CH * CH / 8) return; }
    float4 a = *(const float4*)(src + i * 8);
    float4 b = *(const float4*)(src + i * 8 + 4);
    uint4 o;
    o.x = pack_h2(a.x, a.y); o.y = pack_h2(a.z, a.w);
    o.z = pack_h2(b.x, b.y); o.w = pack_h2(b.z, b.w);
    *(uint4*)(dst + i * 8) = o;
}
__global__ void bias_gather_kernel(const float* __restrict__ table,
                                   const int* __restrict__ ridx) {
    int t = blockIdx.x * 256 + threadIdx.x;
    if (t >= NN) return;
    int r = ridx[t];
    float4 tv = *(const float4*)(table + (size_t)r * 4);
    g_bias[0 * (size_t)NN + t] = __float2half(tv.x * LOG2E);
    g_bias[1 * (size_t)NN + t] = __float2half(tv.y * LOG2E);
    g_bias[2 * (size_t)NN + t] = __float2half(tv.z * LOG2E);
    g_bias[3 * (size_t)NN + t] = __float2half(tv.w * LOG2E);
}
// grid (NWIN, 8)
__global__ void maskflag_kernel(const float* __restrict__ mask) {
    int w = blockIdx.x;
    int slice = blockIdx.y;
    const int SL = NN / 8;                    // 19208
    const float* mp = mask + (size_t)w * NN + (size_t)slice * SL;
    int any = 0;
    for (int i = threadIdx.x; i < SL; i += 256)
        any |= (mp[i] != 0.0f);
    any = __syncthreads_or(any);
    if (threadIdx.x == 0 && any) atomicOr(&g_mflag[w], 1);
}

// ============================================================
// Fused qkv GEMM, M-tile = 128 rows/CTA (grid 1568):
// fp32 x read once (convert while staging); 3 qkv column-tiles
// looped in-kernel with cp.async double-buffered W staging.
// 8 warps = 4 (wm: 32 rows each) x 2 (wn: 64 cols), acc 32x64.
// ============================================================
__global__ void __launch_bounds__(256) gemm_qkv(const float* __restrict__ x) {
    extern __shared__ __half gsm[];
    __half* Xs = gsm;                          // [128][GSTR]
    __half* Wb[2] = { gsm + 128 * GSTR, gsm + (128 + 128) * GSTR };

    int m0 = blockIdx.x * 128;
    int tid = threadIdx.x, lane = tid & 31, warp = tid >> 5;
    int wm = warp >> 1, wn = warp & 1;
    int grp = lane >> 2, q4 = lane & 3;

    // ---- issue cp.async for W tile 0 ----
#pragma unroll
    for (int it = 0; it < 8; it++) {
        int s = tid + it * 256;
        int row = s >> 4, c = s & 15;
        CP_ASYNC16(smem_u32(Wb[0] + row * GSTR + c * 8),
                   g_qkvwh + (size_t)row * CH + c * 8);
    }
    CP_COMMIT();

    // ---- stage X (128 rows, fp32 -> fp16) ----
#pragma unroll
    for (int s = tid; s < 4096; s += 256) {
        int row = s >> 5, c = s & 31;
        float4 xv = *(const float4*)(x + (size_t)(m0 + row) * CH + c * 4);
        uint2 p;
        p.x = pack_h2(xv.x, xv.y);
        p.y = pack_h2(xv.z, xv.w);
        *(uint2*)(Xs + row * GSTR + c * 4) = p;
    }
    CP_WAIT0();
    __syncthreads();

    int tg = lane >> 3, tr = lane & 7;
    int arsel = (tg & 1) ? 8 : 0, acsel = (tg & 2) ? 8 : 0;   // A-frag ldmatrix
    uint32_t xbse0 = smem_u32(Xs + (wm * 32 + arsel + tr) * GSTR + acsel);
    uint32_t xbse1 = xbse0 + (uint32_t)(16 * GSTR * 2);

    int rb = m0 + wm * 32 + grp;
    int rows[4] = { rb, rb + 8, rb + 16, rb + 24 };
    int bi[4], nr[4];
#pragma unroll
    for (int t2 = 0; t2 < 4; t2++) { bi[t2] = rows[t2] / SEQ; nr[t2] = rows[t2] - bi[t2] * SEQ; }

#pragma unroll
    for (int nt = 0; nt < 3; nt++) {
        __half* Wc = Wb[nt & 1];
        if (nt < 2) {
            __half* Wn = Wb[(nt + 1) & 1];
#pragma unroll
            for (int it = 0; it < 8; it++) {
                int s = tid + it * 256;
                int row = s >> 4, c = s & 15;
                CP_ASYNC16(smem_u32(Wn + row * GSTR + c * 8),
                           g_qkvwh + (size_t)((nt + 1) * 128 + row) * CH + c * 8);
            }
            CP_COMMIT();
        }

        uint32_t wbse = smem_u32(Wc + (wn * 64 + ((tg & 2) ? 8 : 0) + tr) * GSTR + ((tg & 1) ? 8 : 0));
        float acc[2][8][4] = {};
#pragma unroll
        for (int ks = 0; ks < 8; ks++) {
            uint32_t xf0[4], xf1[4];
            ldsm_x4(xf0[0], xf0[1], xf0[2], xf0[3], xbse0 + ks * 32);
            ldsm_x4(xf1[0], xf1[1], xf1[2], xf1[3], xbse1 + ks * 32);
#pragma unroll
            for (int jj = 0; jj < 4; jj++) {
                uint32_t wf[4];
                ldsm_x4(wf[0], wf[1], wf[2], wf[3],
                        wbse + (uint32_t)(jj * 16 * GSTR * 2) + ks * 32);
                mma_f16(acc[0][2*jj][0], acc[0][2*jj][1], acc[0][2*jj][2], acc[0][2*jj][3],
                        xf0[0], xf0[1], xf0[2], xf0[3], wf[0], wf[1]);
                mma_f16(acc[0][2*jj+1][0], acc[0][2*jj+1][1], acc[0][2*jj+1][2], acc[0][2*jj+1][3],
                        xf0[0], xf0[1], xf0[2], xf0[3], wf[2], wf[3]);
                mma_f16(acc[1][2*jj][0], acc[1][2*jj][1], acc[1][2*jj][2], acc[1][2*jj][3],
                        xf1[0], xf1[1], xf1[2], xf1[3], wf[0], wf[1]);
                mma_f16(acc[1][2*jj+1][0], acc[1][2*jj+1][1], acc[1][2*jj+1][2], acc[1][2*jj+1][3],
                        xf1[0], xf1[1], xf1[2], xf1[3], wf[2], wf[3]);
            }
        }

        __half* dst = (nt == 0) ? g_q : (nt == 1) ? g_k : g_v;
        float sc = (nt == 0) ? (float)QS_LOG2E : 1.0f;
#pragma unroll
        for (int half = 0; half < 2; half++) {
#pragma unroll
            for (int j = 0; j < 8; j++) {
                int cG = wn * 64 + j * 8;
                int h = cG >> 5;
                int dcol = (cG & 31) + 2 * q4;
                int t0 = half * 2, t1 = half * 2 + 1;
                *(uint32_t*)(dst + ((size_t)((bi[t0] * NHEAD + h) * SEQ) + nr[t0]) * HD + dcol) =
                    pack_h2(acc[half][j][0] * sc, acc[half][j][1] * sc);
                *(uint32_t*)(dst + ((size_t)((bi[t1] * NHEAD + h) * SEQ) + nr[t1]) * HD + dcol) =
                    pack_h2(acc[half][j][2] * sc, acc[half][j][3] * sc);
            }
        }

        if (nt < 2) {
            CP_WAIT0();
            __syncthreads();
        }
    }
}

// ============================================================
// proj GEMM: out[M,128] = ao[M,128] @ projW^T + proj_b
// ============================================================
__global__ void __launch_bounds__(256) gemm_proj(const float* __restrict__ bias,
                                                 float* __restrict__ out) {
    extern __shared__ __half gsm[];
    __half* Xs = gsm;
    __half* Ws = gsm + 64 * GSTR;

    int m0 = blockIdx.x * 64;
    int tid = threadIdx.x, lane = tid & 31, warp = tid >> 5;
    int wm = warp >> 1, wn = warp & 1;
    int grp = lane >> 2, q4 = lane & 3;

#pragma unroll
    for (int s = tid; s < 1024; s += 256) {
        int row = s >> 4, c = s & 15;
        *(uint4*)(Xs + row * GSTR + c * 8) =
            *(const uint4*)(g_ao + (size_t)(m0 + row) * CH + c * 8);
    }
#pragma unroll
    for (int s = tid; s < 2048; s += 256) {
        int row = s >> 4, c = s & 15;
        *(uint4*)(Ws + row * GSTR + c * 8) =
            *(const uint4*)(g_projwh + (size_t)row * CH + c * 8);
    }
    __syncthreads();

    int tg = lane >> 3, tr = lane & 7;
    uint32_t xbse = smem_u32(Xs + (wm * 16 + ((tg & 1) ? 8 : 0) + tr) * GSTR + ((tg & 2) ? 8 : 0));
    uint32_t wbse = smem_u32(Ws + (wn * 64 + ((tg & 2) ? 8 : 0) + tr) * GSTR + ((tg & 1) ? 8 : 0));

    float acc[8][4] = {};
#pragma unroll
    for (int ks = 0; ks < 8; ks++) {
        uint32_t xf[4];
        ldsm_x4(xf[0], xf[1], xf[2], xf[3], xbse + ks * 32);
#pragma unroll
        for (int jj = 0; jj < 4; jj++) {
            uint32_t wf[4];
            ldsm_x4(wf[0], wf[1], wf[2], wf[3],
                    wbse + (uint32_t)(jj * 16 * GSTR * 2) + ks * 32);
            mma_f16(acc[2 * jj][0], acc[2 * jj][1], acc[2 * jj][2], acc[2 * jj][3],
                    xf[0], xf[1], xf[2], xf[3], wf[0], wf[1]);
            mma_f16(acc[2 * jj + 1][0], acc[2 * jj + 1][1], acc[2 * jj + 1][2], acc[2 * jj + 1][3],
                    xf[0], xf[1], xf[2], xf[3], wf[2], wf[3]);
        }
    }

    int r0 = m0 + wm * 16 + grp;
    int r1 = r0 + 8;
#pragma unroll
    for (int j = 0; j < 8; j++) {
        int colb = wn * 64 + j * 8 + 2 * q4;
        float2 pb = *(const float2*)(bias + colb);
        *(float2*)(out + (size_t)r0 * CH + colb) =
            make_float2(acc[j][0] + pb.x, acc[j][1] + pb.y);
        *(float2*)(out + (size_t)r1 * CH + colb) =
            make_float2(acc[j][2] + pb.x, acc[j][3] + pb.y);
    }
}

// ============================================================
// fp16 attention — VERBATIM R14/R16 (measured-good).
// ============================================================
#define ATTN_SMEM (KS_ROWS*KSS*2 + HD*VTS*2)   // 58112 B

__global__ void __launch_bounds__(256, 3) attn_mma(const float* __restrict__ mask) {
    extern __shared__ __half sm[];
    __half* Ks = sm;                    // [400][40]
    __half* Vt = sm + KS_ROWS * KSS;    // [32][408]

    int g = blockIdx.x;
    int w = g >> 4;
    int r = g & 15;
    int b = (r >> 2) * NWIN + w;
    int h = r & 3;
    size_t base = ((size_t)(b * NHEAD + h) * SEQ) * HD;

    int tid = threadIdx.x;
    const uint4 z16 = make_uint4(0, 0, 0, 0);
    for (int s = tid; s < KS_ROWS * 4; s += 256) {
        int row = s >> 2, c = s & 3;
        uint4 kv = (row < SEQ) ? *(const uint4*)(g_k + base + (size_t)row * HD + c * 8) : z16;
        *(uint4*)(Ks + row * KSS + c * 8) = kv;
    }
    for (int s = tid; s < SEQ * 16; s += 256) {
        int row = s >> 4, dp = (s & 15) * 2;
        __half2 v2 = *(const __half2*)(g_v + base + (size_t)row * HD + dp);
        Vt[dp * VTS + row] = v2.x;
        Vt[(dp + 1) * VTS + row] = v2.y;
    }
    for (int s = tid; s < HD * 16; s += 256) {
        int d = s >> 4, c = SEQ + (s & 15);
        Vt[d * VTS + c] = __half(0.0f);
    }
    __syncthreads();

    bool domask = (g_mflag[w] != 0);
    int lane = tid & 31, warp = tid >> 5;
    int grp = lane >> 2, q4 = lane & 3;

    int tg = lane >> 3, tr = lane & 7;
    int rsel = (tg & 2) ? 8 : 0;
    int csel = (tg & 1) ? 8 : 0;
    uint32_t kb = smem_u32(Ks + (rsel + tr) * KSS + csel);
    uint32_t vb = smem_u32(Vt + (rsel + tr) * VTS + csel);

    const __half* biasp = g_bias + (size_t)h * NN;
    const float* maskp = mask + (size_t)w * NN;

    for (int mt = warp; mt < MT; mt += 8) {
        int m0 = mt * 16;
        int row0 = m0 + grp;
        int row1 = row0 + 8;
        int r1c = (row1 < SEQ) ? row1 : SEQ - 1;

        const __half* q0p = g_q + base + (size_t)row0 * HD;
        const __half* q1p = g_q + base + (size_t)r1c * HD;
        uint32_t aq[2][4];
#pragma unroll
        for (int ks = 0; ks < 2; ks++) {
            aq[ks][0] = *(const uint32_t*)(q0p + ks * 16 + 2 * q4);
            aq[ks][1] = *(const uint32_t*)(q1p + ks * 16 + 2 * q4);
            aq[ks][2] = *(const uint32_t*)(q0p + ks * 16 + 2 * q4 + 8);
            aq[ks][3] = *(const uint32_t*)(q1p + ks * 16 + 2 * q4 + 8);
        }

        const __half* b0r = biasp + (size_t)row0 * SEQ + 2 * q4;
        const __half* b1r = biasp + (size_t)r1c * SEQ + 2 * q4;
        const float* m0r = maskp + (size_t)row0 * SEQ + 2 * q4;
        const float* m1r = maskp + (size_t)r1c * SEQ + 2 * q4;

        float oacc[4][4] = {};
        float rs0 = 0.0f, rs1 = 0.0f;

        uint32_t pb0 = *(const uint32_t*)(b0r);
        uint32_t pb1 = *(const uint32_t*)(b1r);
        uint32_t pb2 = *(const uint32_t*)(b0r + 8);
        uint32_t pb3 = *(const uint32_t*)(b1r + 8);

        for (int nt = 0; nt < NT16; nt++) {
            int n0 = nt * 16;
            bool tail = (nt == NT16 - 1);

            uint32_t kf0[4], kf1[4];
            uint32_t kaddr = kb + (uint32_t)(n0 * (KSS * 2));
            ldsm_x4(kf0[0], kf0[1], kf0[2], kf0[3], kaddr);
            ldsm_x4(kf1[0], kf1[1], kf1[2], kf1[3], kaddr + 32);

            uint32_t nb0 = 0, nb1 = 0, nb2 = 0, nb3 = 0;
            if (!tail) {
                int nn = n0 + 16;
                nb0 = *(const uint32_t*)(b0r + nn);
                nb1 = *(const uint32_t*)(b1r + nn);
                nb2 = *(const uint32_t*)(b0r + nn + 8);
                nb3 = *(const uint32_t*)(b1r + nn + 8);
            }

            float cL0 = 0.f, cL1 = 0.f, cL2 = 0.f, cL3 = 0.f;
            float cR0 = 0.f, cR1 = 0.f, cR2 = 0.f, cR3 = 0.f;
            mma_f16(cL0, cL1, cL2, cL3, aq[0][0], aq[0][1], aq[0][2], aq[0][3], kf0[0], kf0[1]);
            mma_f16(cR0, cR1, cR2, cR3, aq[0][0], aq[0][1], aq[0][2], aq[0][3], kf0[2], kf0[3]);
            mma_f16(cL0, cL1, cL2, cL3, aq[1][0], aq[1][1], aq[1][2], aq[1][3], kf1[0], kf1[1]);
            mma_f16(cR0, cR1, cR2, cR3, aq[1][0], aq[1][1], aq[1][2], aq[1][3], kf1[2], kf1[3]);

            float2 bL0f = __half22float2(*reinterpret_cast<__half2*>(&pb0));
            float2 bL1f = __half22float2(*reinterpret_cast<__half2*>(&pb1));
            if (domask) {
                float2 mm0 = *(const float2*)(m0r + n0);
                float2 mm1 = *(const float2*)(m1r + n0);
                bL0f.x += mm0.x * LOG2E; bL0f.y += mm0.y * LOG2E;
                bL1f.x += mm1.x * LOG2E; bL1f.y += mm1.y * LOG2E;
            }
            float eL0 = ex2f(cL0 + bL0f.x), eL1 = ex2f(cL1 + bL0f.y);
            float eL2 = ex2f(cL2 + bL1f.x), eL3 = ex2f(cL3 + bL1f.y);

            float eR0 = 0.f, eR1 = 0.f, eR2 = 0.f, eR3 = 0.f;
            if (!tail) {
                float2 bR0f = __half22float2(*reinterpret_cast<__half2*>(&pb2));
                float2 bR1f = __half22float2(*reinterpret_cast<__half2*>(&pb3));
                if (domask) {
                    float2 mm0 = *(const float2*)(m0r + n0 + 8);
                    float2 mm1 = *(const float2*)(m1r + n0 + 8);
                    bR0f.x += mm0.x * LOG2E; bR0f.y += mm0.y * LOG2E;
                    bR1f.x += mm1.x * LOG2E; bR1f.y += mm1.y * LOG2E;
                }
                eR0 = ex2f(cR0 + bR0f.x); eR1 = ex2f(cR1 + bR0f.y);
                eR2 = ex2f(cR2 + bR1f.x); eR3 = ex2f(cR3 + bR1f.y);
            }

            rs0 += (eL0 + eL1) + (eR0 + eR1);
            rs1 += (eL2 + eL3) + (eR2 + eR3);

            uint32_t ap0 = pack_h2(eL0, eL1);
            uint32_t ap1 = pack_h2(eL2, eL3);
            uint32_t ap2 = pack_h2(eR0, eR1);
            uint32_t ap3 = pack_h2(eR2, eR3);

            uint32_t vf0[4], vf1[4];
            uint32_t vaddr = vb + (uint32_t)(n0 * 2);
            ldsm_x4(vf0[0], vf0[1], vf0[2], vf0[3], vaddr);
            ldsm_x4(vf1[0], vf1[1], vf1[2], vf1[3], vaddr + 16 * VTS * 2);
            mma_f16(oacc[0][0], oacc[0][1], oacc[0][2], oacc[0][3], ap0, ap1, ap2, ap3, vf0[0], vf0[1]);
            mma_f16(oacc[1][0], oacc[1][1], oacc[1][2], oacc[1][3], ap0, ap1, ap2, ap3, vf0[2], vf0[3]);
            mma_f16(oacc[2][0], oacc[2][1], oacc[2][2], oacc[2][3], ap0, ap1, ap2, ap3, vf1[0], vf1[1]);
            mma_f16(oacc[3][0], oacc[3][1], oacc[3][2], oacc[3][3], ap0, ap1, ap2, ap3, vf1[2], vf1[3]);

            pb0 = nb0; pb1 = nb1; pb2 = nb2; pb3 = nb3;
        }

        rs0 += __shfl_xor_sync(0xffffffffu, rs0, 1);
        rs0 += __shfl_xor_sync(0xffffffffu, rs0, 2);
        rs1 += __shfl_xor_sync(0xffffffffu, rs1, 1);
        rs1 += __shfl_xor_sync(0xffffffffu, rs1, 2);
        float inv0 = __frcp_rn(rs0), inv1 = __frcp_rn(rs1);

        {
            __half* op = g_ao + ((size_t)b * SEQ + row0) * CH + h * HD + 2 * q4;
#pragma unroll
            for (int j = 0; j < 4; j++)
                *(uint32_t*)(op + j * 8) = pack_h2(oacc[j][0] * inv0, oacc[j][1] * inv0);
        }
        if (row1 < SEQ) {
            __half* op = g_ao + ((size_t)b * SEQ + row1) * CH + h * HD + 2 * q4;
#pragma unroll
            for (int j = 0; j < 4; j++)
                *(uint32_t*)(op + j * 8) = pack_h2(oacc[j][2] * inv1, oacc[j][3] * inv1);
        }
    }
}

// ============================================================
extern "C" void kernel_launch(void* const* d_in, const int* in_sizes, int n_in,
                              void* d_out, int out_size) {
    (void)in_sizes; (void)n_in; (void)out_size;
    const float* x          = (const float*)d_in[0];
    const float* mask       = (const float*)d_in[1];
    const float* qkv_w      = (const float*)d_in[2];
    const float* proj_w     = (const float*)d_in[3];
    const float* proj_b     = (const float*)d_in[4];
    const float* bias_table = (const float*)d_in[5];
    const int*   rel_index  = (const int*)d_in[6];
    float* out = (float*)d_out;

    cudaFuncSetAttribute(attn_mma, cudaFuncAttributeMaxDynamicSharedMemorySize, ATTN_SMEM);
    cudaFuncSetAttribute(gemm_qkv, cudaFuncAttributeMaxDynamicSharedMemorySize, GSMEM_QKV);
    cudaFuncSetAttribute(gemm_proj, cudaFuncAttributeMaxDynamicSharedMemorySize, GSMEM_PRJ);

    convert_w_kernel<<<((384 * CH + CH * CH) / 8 + 255) / 256, 256>>>(qkv_w, proj_w);
    bias_gather_kernel<<<(NN + 255) / 256, 256>>>(bias_table, rel_index);
    maskflag_kernel<<<dim3(NWIN, 8), 256>>>(mask);
    gemm_qkv<<<MROWS / 128, 256, GSMEM_QKV>>>(x);
    attn_mma<<<B_TOT * NHEAD, 256, ATTN_SMEM>>>(mask);
    gemm_proj<<<MROWS / 64, 256, GSMEM_PRJ>>>(proj_b, out);
}